// round 7
// baseline (speedup 1.0000x reference)
#include <cuda_runtime.h>
#include <cstdint>

// Problem constants
constexpr int NB = 16;
constexpr int NC = 128;
constexpr int NH = 64;
constexpr int NW = 64;
constexpr int HW = NH * NW;
constexpr int NOC = 128;

// Scratch (allocation-free rule: __device__ globals)
__device__ float g_T[NB * 2 * HW];          // per-parity channel sums
__device__ float g_avg[NB * 2 * HW];        // 3x3 box mean / 576
__device__ float g_W2[NOC * 2];             // sum of weights per (o, parity)
__device__ float g_wdup[NOC * NC * 9 * 2];  // weights duplicated {w,w} for LDS.64

typedef unsigned long long u64;

// ---------------------------------------------------------------------------
// packed f32x2 helpers (FFMA2 — reachable only via PTX fma.rn.f32x2)
// ---------------------------------------------------------------------------
#define FFMA2(d, a, b, c) \
    asm("fma.rn.f32x2 %0, %1, %2, %3;" : "=l"(d) : "l"(a), "l"(b), "l"(c))
#define PACKF2(d, lo, hi) \
    asm("mov.b64 %0, {%1, %2};" : "=l"(d) : "f"(lo), "f"(hi))
#define UNPACKF2(lo, hi, s) \
    asm("mov.b64 {%0, %1}, %2;" : "=f"(lo), "=f"(hi) : "l"(s))

// ---------------------------------------------------------------------------
// cp.async helpers
// ---------------------------------------------------------------------------
__device__ __forceinline__ void cp_async4(void* smem_ptr, const void* gmem_ptr) {
    uint32_t s = (uint32_t)__cvta_generic_to_shared(smem_ptr);
    asm volatile("cp.async.ca.shared.global [%0], [%1], 4;" :: "r"(s), "l"(gmem_ptr));
}
__device__ __forceinline__ void cp_async8(void* smem_ptr, const void* gmem_ptr) {
    uint32_t s = (uint32_t)__cvta_generic_to_shared(smem_ptr);
    asm volatile("cp.async.ca.shared.global [%0], [%1], 8;" :: "r"(s), "l"(gmem_ptr));
}
__device__ __forceinline__ void cp_commit() {
    asm volatile("cp.async.commit_group;");
}
template <int N>
__device__ __forceinline__ void cp_wait() {
    asm volatile("cp.async.wait_group %0;" :: "n"(N));
}

// ---------------------------------------------------------------------------
// Kernel 1: per-pixel channel-parity sums  T[b,u,y,x] = sum_{c%2==u} x[b,c,y,x]
// ---------------------------------------------------------------------------
__global__ void parity_sum_kernel(const float* __restrict__ x) {
    int idx = blockIdx.x * blockDim.x + threadIdx.x;  // b*HW + pix
    if (idx >= NB * HW) return;
    int b = idx / HW;
    int pix = idx - b * HW;
    const float* xp = x + (size_t)b * NC * HW + pix;
    float s0 = 0.f, s1 = 0.f;
#pragma unroll 8
    for (int c = 0; c < NC; c += 2) {
        s0 += xp[(size_t)c * HW];
        s1 += xp[(size_t)(c + 1) * HW];
    }
    g_T[(b * 2 + 0) * HW + pix] = s0;
    g_T[(b * 2 + 1) * HW + pix] = s1;
}

// ---------------------------------------------------------------------------
// Kernel 2: 3x3 edge-clamped box filter / 576 -> g_avg
// ---------------------------------------------------------------------------
__global__ void avg_kernel() {
    int idx = blockIdx.x * blockDim.x + threadIdx.x;  // (b*2+u)*HW + pix
    if (idx >= NB * 2 * HW) return;
    int bu = idx / HW;
    int pix = idx - bu * HW;
    int i = pix / NW, j = pix - (pix / NW) * NW;
    const float* T = g_T + bu * HW;
    float s = 0.f;
#pragma unroll
    for (int r = -1; r <= 1; r++) {
        int y = min(max(i + r, 0), NH - 1);
#pragma unroll
        for (int q = -1; q <= 1; q++) {
            int xw = min(max(j + q, 0), NW - 1);
            s += T[y * NW + xw];
        }
    }
    g_avg[idx] = s * (1.0f / 576.0f);
}

// ---------------------------------------------------------------------------
// Kernel 3: W2[o,u] = sum_{c%2==u} sum_{r,s} w[o,c,r,s]   (one block per o)
// ---------------------------------------------------------------------------
__global__ void w2_kernel(const float* __restrict__ w) {
    __shared__ float s2[2];
    int o = blockIdx.x;
    int c = threadIdx.x;  // 0..127
    if (c < 2) s2[c] = 0.f;
    __syncthreads();
    const float* wp = w + ((size_t)o * NC + c) * 9;
    float s = 0.f;
#pragma unroll
    for (int k = 0; k < 9; k++) s += wp[k];
    atomicAdd(&s2[c & 1], s);
    __syncthreads();
    if (c < 2) g_W2[o * 2 + c] = s2[c];
}

// ---------------------------------------------------------------------------
// Kernel 3b: duplicate weights -> g_wdup[i] = {w[i], w[i]}
// ---------------------------------------------------------------------------
__global__ void wdup_kernel(const float* __restrict__ w) {
    int idx = blockIdx.x * blockDim.x + threadIdx.x;  // o*NC*9 range
    if (idx >= NOC * NC * 9) return;
    float v = w[idx];
    g_wdup[idx * 2 + 0] = v;
    g_wdup[idx * 2 + 1] = v;
}

// ---------------------------------------------------------------------------
// Kernel 4: fused conv + bias + mean-correction + LeakyReLU + parity-mean add.
// Block: 32(x) x 16(y) spatial tile, 32 output channels, one batch.
// Thread: 8 oc x 4 packed-pixel-pairs (x: tx & tx+16, y: 4 rows) via FFMA2.
// Double-buffered cp.async prefetch over channels.
// ---------------------------------------------------------------------------
constexpr int TX = 32;
constexpr int TY = 16;
constexpr int OCT = 32;

__global__ __launch_bounds__(256, 2) void conv_kernel(
    const float* __restrict__ x,
    const float* __restrict__ bias, float* __restrict__ out) {
    __shared__ float s_x[2][TY + 2][TX + 4];                  // 2 x 18 x 36 (34 used)
    __shared__ __align__(8) float s_wd[2][9][OCT][2];         // duplicated weights
    __shared__ float s_bias[OCT];
    __shared__ float s_w2[OCT][2];

    int b = blockIdx.z;
    int ocb = blockIdx.y * OCT;
    int tileX = (blockIdx.x & 1) * TX;         // 2 tiles in x
    int tileY = (blockIdx.x >> 1) * TY;        // 4 tiles in y

    int t = threadIdx.x;
    int tx = t & 15;         // 0..15 (pixel pair: cols tx, tx+16)
    int ty = (t >> 4) & 3;   // 0..3  -> 4 px each in y
    int oz = t >> 6;         // 0..3  -> 8 oc each

    if (t < OCT) s_bias[t] = bias[ocb + t];
    if (t < OCT * 2) s_w2[t >> 1][t & 1] = g_W2[(ocb + (t >> 1)) * 2 + (t & 1)];

    u64 acc2[8][4];
#pragma unroll
    for (int a = 0; a < 8; a++)
#pragma unroll
        for (int p = 0; p < 4; p++) acc2[a][p] = 0ull;

    const float* xb = x + (size_t)b * NC * HW;

    // async load of one channel (x tile + duplicated weights) into buffer `buf`
    auto load_ch = [&](int c, int buf) {
#pragma unroll
        for (int l = t; l < 18 * 34; l += 256) {
            int ly = l / 34, lx = l - ly * 34;
            int gy = min(max(tileY - 1 + ly, 0), NH - 1);
            int gx = min(max(tileX - 1 + lx, 0), NW - 1);
            cp_async4(&s_x[buf][ly][lx], &xb[(size_t)c * HW + gy * NW + gx]);
        }
#pragma unroll
        for (int l = t; l < OCT * 9; l += 256) {
            int o = l / 9, k = l - o * 9;
            cp_async8(&s_wd[buf][k][o][0],
                      &g_wdup[(((size_t)(ocb + o) * NC + c) * 9 + k) * 2]);
        }
    };

    load_ch(0, 0);
    cp_commit();

    for (int c = 0; c < NC; c++) {
        int buf = c & 1;
        if (c + 1 < NC) {
            load_ch(c + 1, buf ^ 1);   // prefetch next channel
            cp_commit();
            cp_wait<1>();              // buffer `buf` (older group) complete
        } else {
            cp_wait<0>();
        }
        __syncthreads();               // buffer `buf` visible to all threads

        // taps: weight w[o,c,r,s] pairs with input offset (row += s, col += r)
#pragma unroll
        for (int r = 0; r < 3; r++) {
#pragma unroll
            for (int s = 0; s < 3; s++) {
                u64 xv2[4];
#pragma unroll
                for (int yy = 0; yy < 4; yy++) {
                    float x0 = s_x[buf][ty * 4 + yy + s][tx + r];
                    float x1 = s_x[buf][ty * 4 + yy + s][tx + 16 + r];
                    PACKF2(xv2[yy], x0, x1);
                }
#pragma unroll
                for (int a = 0; a < 8; a++) {
                    u64 wv2 = *reinterpret_cast<const u64*>(
                        &s_wd[buf][r * 3 + s][oz * 8 + a][0]);   // LDS.64 broadcast
#pragma unroll
                    for (int p = 0; p < 4; p++)
                        FFMA2(acc2[a][p], xv2[p], wv2, acc2[a][p]);
                }
            }
        }
        __syncthreads();               // all reads of `buf` done before overwrite
    }

    // epilogue
    const float* avg0 = g_avg + (b * 2 + 0) * HW;
    const float* avg1 = g_avg + (b * 2 + 1) * HW;
#pragma unroll
    for (int yy = 0; yy < 4; yy++) {
        int i = tileY + ty * 4 + yy;
#pragma unroll
        for (int a = 0; a < 8; a++) {
            int o = ocb + oz * 8 + a;
            float v0, v1;
            UNPACKF2(v0, v1, acc2[a][yy]);
            float bw = s_bias[oz * 8 + a];
            float w20 = s_w2[oz * 8 + a][0];
            float w21 = s_w2[oz * 8 + a][1];
#pragma unroll
            for (int xx = 0; xx < 2; xx++) {
                int j = tileX + tx + 16 * xx;
                float a0 = avg0[i * NW + j];
                float a1 = avg1[i * NW + j];
                float v = (xx ? v1 : v0) + bw - w20 * a0 - w21 * a1;
                v = v > 0.f ? v : 0.01f * v;
                v += (o & 1) ? a1 : a0;
                out[((size_t)b * NOC + o) * HW + i * NW + j] = v;
            }
        }
    }
}

// ---------------------------------------------------------------------------
extern "C" void kernel_launch(void* const* d_in, const int* in_sizes, int n_in,
                              void* d_out, int out_size) {
    const float* x = (const float*)d_in[0];     // (16,128,64,64)
    const float* w = (const float*)d_in[1];     // (128,128,3,3)
    const float* bias = (const float*)d_in[2];  // (128,)
    float* out = (float*)d_out;                 // (16,128,64,64)

    parity_sum_kernel<<<(NB * HW + 255) / 256, 256>>>(x);
    avg_kernel<<<(NB * 2 * HW + 255) / 256, 256>>>();
    w2_kernel<<<NOC, 128>>>(w);
    wdup_kernel<<<(NOC * NC * 9 + 255) / 256, 256>>>(w);

    dim3 grid(8, NOC / OCT, NB);  // 8 spatial tiles x 4 oc-groups x 16 batches
    conv_kernel<<<grid, 256>>>(x, bias, out);
}

// round 8
// speedup vs baseline: 2.7485x; 2.7485x over previous
#include <cuda_runtime.h>
#include <cstdint>

// Problem constants
constexpr int NB = 16;
constexpr int NC = 128;
constexpr int NH = 64;
constexpr int NW = 64;
constexpr int HW = NH * NW;
constexpr int NOC = 128;

// Scratch (allocation-free rule: __device__ globals)
__device__ float g_T[NB * 2 * HW];        // per-parity channel sums
__device__ float g_avg[NB * 2 * HW];      // 3x3 box mean / 576
__device__ float g_W2[NOC * 2];           // sum of weights per (o, parity)
__device__ __align__(16) float g_wre[9 * NOC * NC];  // w reordered [tap][oc][c], tf32-rounded

// ---------------------------------------------------------------------------
// helpers
// ---------------------------------------------------------------------------
__device__ __forceinline__ uint32_t f2tf(float f) {
    uint32_t u;
    asm("cvt.rna.tf32.f32 %0, %1;" : "=r"(u) : "f"(f));
    return u;
}
__device__ __forceinline__ void mma_tf32(float* c, uint32_t a0, uint32_t a1,
                                         uint32_t a2, uint32_t a3,
                                         uint32_t b0, uint32_t b1) {
    asm volatile(
        "mma.sync.aligned.m16n8k8.row.col.f32.tf32.tf32.f32 "
        "{%0,%1,%2,%3}, {%4,%5,%6,%7}, {%8,%9}, {%0,%1,%2,%3};"
        : "+f"(c[0]), "+f"(c[1]), "+f"(c[2]), "+f"(c[3])
        : "r"(a0), "r"(a1), "r"(a2), "r"(a3), "r"(b0), "r"(b1));
}
__device__ __forceinline__ void cp_async4(void* smem_ptr, const void* gmem_ptr) {
    uint32_t s = (uint32_t)__cvta_generic_to_shared(smem_ptr);
    asm volatile("cp.async.ca.shared.global [%0], [%1], 4;" :: "r"(s), "l"(gmem_ptr));
}
__device__ __forceinline__ void cp_async16(void* smem_ptr, const void* gmem_ptr) {
    uint32_t s = (uint32_t)__cvta_generic_to_shared(smem_ptr);
    asm volatile("cp.async.cg.shared.global [%0], [%1], 16;" :: "r"(s), "l"(gmem_ptr));
}
__device__ __forceinline__ void cp_commit() { asm volatile("cp.async.commit_group;"); }
template <int N>
__device__ __forceinline__ void cp_wait() {
    asm volatile("cp.async.wait_group %0;" :: "n"(N));
}

// ---------------------------------------------------------------------------
// Kernel 1: per-pixel channel-parity sums
// ---------------------------------------------------------------------------
__global__ void parity_sum_kernel(const float* __restrict__ x) {
    int idx = blockIdx.x * blockDim.x + threadIdx.x;
    if (idx >= NB * HW) return;
    int b = idx / HW;
    int pix = idx - b * HW;
    const float* xp = x + (size_t)b * NC * HW + pix;
    float s0 = 0.f, s1 = 0.f;
#pragma unroll 8
    for (int c = 0; c < NC; c += 2) {
        s0 += xp[(size_t)c * HW];
        s1 += xp[(size_t)(c + 1) * HW];
    }
    g_T[(b * 2 + 0) * HW + pix] = s0;
    g_T[(b * 2 + 1) * HW + pix] = s1;
}

// ---------------------------------------------------------------------------
// Kernel 2: 3x3 edge-clamped box filter / 576 -> g_avg
// ---------------------------------------------------------------------------
__global__ void avg_kernel() {
    int idx = blockIdx.x * blockDim.x + threadIdx.x;
    if (idx >= NB * 2 * HW) return;
    int bu = idx / HW;
    int pix = idx - bu * HW;
    int i = pix / NW, j = pix - (pix / NW) * NW;
    const float* T = g_T + bu * HW;
    float s = 0.f;
#pragma unroll
    for (int r = -1; r <= 1; r++) {
        int y = min(max(i + r, 0), NH - 1);
#pragma unroll
        for (int q = -1; q <= 1; q++) {
            int xw = min(max(j + q, 0), NW - 1);
            s += T[y * NW + xw];
        }
    }
    g_avg[idx] = s * (1.0f / 576.0f);
}

// ---------------------------------------------------------------------------
// Kernel 3: W2[o,u] = sum_{c%2==u} sum_{r,s} w[o,c,r,s]   (fp32, original w)
// ---------------------------------------------------------------------------
__global__ void w2_kernel(const float* __restrict__ w) {
    __shared__ float s2[2];
    int o = blockIdx.x;
    int c = threadIdx.x;  // 0..127
    if (c < 2) s2[c] = 0.f;
    __syncthreads();
    const float* wp = w + ((size_t)o * NC + c) * 9;
    float s = 0.f;
#pragma unroll
    for (int k = 0; k < 9; k++) s += wp[k];
    atomicAdd(&s2[c & 1], s);
    __syncthreads();
    if (c < 2) g_W2[o * 2 + c] = s2[c];
}

// ---------------------------------------------------------------------------
// Kernel 3b: reorder weights -> g_wre[tap][oc][c], rounded to tf32
// ---------------------------------------------------------------------------
__global__ void wre_kernel(const float* __restrict__ w) {
    int idx = blockIdx.x * blockDim.x + threadIdx.x;
    if (idx >= NOC * NC * 9) return;
    int tap = idx % 9;
    int rem = idx / 9;          // oc*128 + c
    int oc = rem / NC;
    int c = rem - oc * NC;
    float v = w[((size_t)oc * NC + c) * 9 + tap];
    g_wre[(tap * NOC + oc) * NC + c] = __uint_as_float(f2tf(v));
}

// ---------------------------------------------------------------------------
// Kernel 4: implicit-GEMM conv via mma.sync tf32 + fused epilogue.
// CTA: 4 rows x 32 cols pixel tile (128 px), all 128 oc. 8 warps (4M x 2N).
// K loop: 4 c-chunks of 32 x 9 taps, cp.async double-buffered.
//
// k-permutation: mma k-slot l -> c=2l, slot l+4 -> c=2l+1, so A pairs
// (a0,a2),(a1,a3) and B pair (b0,b1) are contiguous LDS.64.
// x smem: [c2(16)][plane 456 floats = 6 rows x 76 (38 colpairs x 2)]
//   -> B pair-bank = 4l + g + const (conflict-free).
// w smem: [oc(128)][40 floats] -> A pair-bank = 4g + l + const (conflict-free).
// ---------------------------------------------------------------------------
constexpr int XPLANE = 456;                 // floats per c2 plane (228 pairs == 4 mod 16)
constexpr int XBUF = 16 * XPLANE;           // 7296 floats
constexpr int WROW = 40;                    // floats per oc row (20 pairs == 4 mod 16)
constexpr int WBUF = NOC * WROW;            // 5120 floats
constexpr int SMEM_FLOATS = 2 * XBUF + 2 * WBUF + NOC + 2 * NOC;
constexpr int SMEM_BYTES = SMEM_FLOATS * 4; // 100864 B

__global__ __launch_bounds__(256, 2) void conv_mma_kernel(
    const float* __restrict__ x, const float* __restrict__ bias,
    float* __restrict__ out) {
    extern __shared__ __align__(16) float smem[];
    float* xs = smem;                       // [2][XBUF]
    float* ws = smem + 2 * XBUF;            // [2][WBUF]
    float* s_bias = ws + 2 * WBUF;          // [128]
    float* s_w2 = s_bias + NOC;             // [256]

    int b = blockIdx.z;
    int col0 = (blockIdx.x & 1) * 32;
    int row0 = (blockIdx.x >> 1) * 4;

    int t = threadIdx.x;
    int wid = t >> 5, lane = t & 31;
    int g = lane >> 2, l = lane & 3;
    int wm = wid >> 1, wn = wid & 1;

    if (t < NOC) s_bias[t] = bias[t];
    if (t < 2 * NOC) s_w2[t] = g_W2[t];

    const float* xb = x + (size_t)b * NC * HW;

    // ---- async loaders ----
    auto load_x = [&](int cc, int buf) {
        float* dst = xs + buf * XBUF;
        const float* src = xb + (size_t)cc * 32 * HW;
#pragma unroll 1
        for (int e = t; e < 32 * 204; e += 256) {
            int c = e / 204;
            int rem = e - c * 204;
            int sr = rem / 34;
            int sc = rem - sr * 34;
            int gy = min(max(row0 - 1 + sr, 0), NH - 1);
            int gx = min(max(col0 - 1 + sc, 0), NW - 1);
            cp_async4(dst + (c >> 1) * XPLANE + sr * 76 + sc * 2 + (c & 1),
                      src + (size_t)c * HW + gy * NW + gx);
        }
    };
    auto load_w = [&](int cc, int tap, int buf) {
        float* dst = ws + buf * WBUF;
        const float* src = g_wre + (size_t)tap * NOC * NC + cc * 32;
#pragma unroll
        for (int e = t; e < NOC * 8; e += 256) {
            int oc = e >> 3;
            int q16 = e & 7;
            cp_async16(dst + oc * WROW + q16 * 4, src + oc * NC + q16 * 4);
        }
    };

    float acc[2][8][4];
#pragma unroll
    for (int mt = 0; mt < 2; mt++)
#pragma unroll
        for (int nt = 0; nt < 8; nt++)
#pragma unroll
            for (int k = 0; k < 4; k++) acc[mt][nt][k] = 0.f;

    load_x(0, 0);
    load_w(0, 0, 0);
    cp_commit();

#pragma unroll 1
    for (int step = 0; step < 36; step++) {
        int cc = step / 9;
        int tap = step - cc * 9;
        int nstep = step + 1;
        if (nstep < 36) {
            int ncc = nstep / 9;
            int ntap = nstep - ncc * 9;
            if (ntap == 0) load_x(ncc, ncc & 1);
            load_w(ncc, ntap, nstep & 1);
            cp_commit();
            cp_wait<1>();
        } else {
            cp_wait<0>();
        }
        __syncthreads();

        int r = tap / 3;           // col shift
        int sft = tap - r * 3;     // row shift
        // B base: c2 = l (+4q), pixel row = wn*2 + (nt>>2) + sft, col = (nt&3)*8 + g + r
        const float* Bbase = xs + (cc & 1) * XBUF + l * XPLANE +
                             (wn * 2 + sft) * 76 + (g + r) * 2;
        // A base: row = wm*32 + mt*16 + g (+8), c = 8q + 2l
        const float* Abase = ws + (step & 1) * WBUF + (wm * 32 + g) * WROW + 2 * l;

#pragma unroll
        for (int q = 0; q < 4; q++) {
            uint32_t A[2][4];
#pragma unroll
            for (int mt = 0; mt < 2; mt++) {
                float2 p0 = *(const float2*)(Abase + mt * (16 * WROW) + q * 8);
                float2 p1 = *(const float2*)(Abase + mt * (16 * WROW) + 8 * WROW + q * 8);
                A[mt][0] = __float_as_uint(p0.x);  // pre-rounded tf32
                A[mt][2] = __float_as_uint(p0.y);
                A[mt][1] = __float_as_uint(p1.x);
                A[mt][3] = __float_as_uint(p1.y);
            }
#pragma unroll
            for (int nt = 0; nt < 8; nt++) {
                float2 bp = *(const float2*)(Bbase + q * (4 * XPLANE) +
                                             (nt >> 2) * 76 + (nt & 3) * 16);
                uint32_t b0 = f2tf(bp.x);
                uint32_t b1 = f2tf(bp.y);
                mma_tf32(acc[0][nt], A[0][0], A[0][1], A[0][2], A[0][3], b0, b1);
                mma_tf32(acc[1][nt], A[1][0], A[1][1], A[1][2], A[1][3], b0, b1);
            }
        }
        __syncthreads();
    }

    // ---- epilogue: bias - W2*avg, leaky, + parity mean ----
    const float* avg0 = g_avg + (b * 2 + 0) * HW;
    const float* avg1 = g_avg + (b * 2 + 1) * HW;
#pragma unroll
    for (int nt = 0; nt < 8; nt++) {
        int i = row0 + wn * 2 + (nt >> 2);
        int j = col0 + (nt & 3) * 8 + 2 * l;
        float2 a0 = *(const float2*)(avg0 + i * NW + j);
        float2 a1 = *(const float2*)(avg1 + i * NW + j);
#pragma unroll
        for (int mt = 0; mt < 2; mt++) {
#pragma unroll
            for (int half = 0; half < 2; half++) {
                int o = wm * 32 + mt * 16 + half * 8 + g;
                float bw = s_bias[o];
                float w20 = s_w2[2 * o], w21 = s_w2[2 * o + 1];
                float v0 = acc[mt][nt][half * 2 + 0] + bw - w20 * a0.x - w21 * a1.x;
                float v1 = acc[mt][nt][half * 2 + 1] + bw - w20 * a0.y - w21 * a1.y;
                v0 = v0 > 0.f ? v0 : 0.01f * v0;
                v1 = v1 > 0.f ? v1 : 0.01f * v1;
                if (o & 1) { v0 += a1.x; v1 += a1.y; }
                else       { v0 += a0.x; v1 += a0.y; }
                float2 vv = make_float2(v0, v1);
                *(float2*)(out + ((size_t)(b * NOC + o)) * HW + i * NW + j) = vv;
            }
        }
    }
}

// ---------------------------------------------------------------------------
extern "C" void kernel_launch(void* const* d_in, const int* in_sizes, int n_in,
                              void* d_out, int out_size) {
    const float* x = (const float*)d_in[0];     // (16,128,64,64)
    const float* w = (const float*)d_in[1];     // (128,128,3,3)
    const float* bias = (const float*)d_in[2];  // (128,)
    float* out = (float*)d_out;                 // (16,128,64,64)

    cudaFuncSetAttribute(conv_mma_kernel,
                         cudaFuncAttributeMaxDynamicSharedMemorySize, SMEM_BYTES);

    parity_sum_kernel<<<(NB * HW + 255) / 256, 256>>>(x);
    avg_kernel<<<(NB * 2 * HW + 255) / 256, 256>>>();
    w2_kernel<<<NOC, 128>>>(w);
    wre_kernel<<<(NOC * NC * 9 + 255) / 256, 256>>>(w);

    dim3 grid(32, 1, NB);  // 32 pixel tiles (2x in x, 16 in y) x 16 batches
    conv_mma_kernel<<<grid, 256, SMEM_BYTES>>>(x, bias, out);
}

// round 10
// speedup vs baseline: 2.7530x; 1.0017x over previous
#include <cuda_runtime.h>
#include <cstdint>

// Problem constants
constexpr int NB = 16;
constexpr int NC = 128;
constexpr int NH = 64;
constexpr int NW = 64;
constexpr int HW = NH * NW;
constexpr int NOC = 128;

// Scratch (allocation-free rule: __device__ globals)
__device__ float g_T[NB * 2 * HW];        // per-parity channel sums
__device__ float g_avg[NB * 2 * HW];      // 3x3 box mean / 576
__device__ float g_W2[NOC * 2];           // sum of weights per (o, parity)
__device__ __align__(16) float g_wre[9 * NOC * NC];  // w reordered [tap][oc][c], tf32-rounded

// ---------------------------------------------------------------------------
// helpers
// ---------------------------------------------------------------------------
__device__ __forceinline__ uint32_t f2tf(float f) {
    uint32_t u;
    asm("cvt.rna.tf32.f32 %0, %1;" : "=r"(u) : "f"(f));
    return u;
}
__device__ __forceinline__ void mma_tf32(float* c, uint32_t a0, uint32_t a1,
                                         uint32_t a2, uint32_t a3,
                                         uint32_t b0, uint32_t b1) {
    asm volatile(
        "mma.sync.aligned.m16n8k8.row.col.f32.tf32.tf32.f32 "
        "{%0,%1,%2,%3}, {%4,%5,%6,%7}, {%8,%9}, {%0,%1,%2,%3};"
        : "+f"(c[0]), "+f"(c[1]), "+f"(c[2]), "+f"(c[3])
        : "r"(a0), "r"(a1), "r"(a2), "r"(a3), "r"(b0), "r"(b1));
}
__device__ __forceinline__ void cp_async4(void* smem_ptr, const void* gmem_ptr) {
    uint32_t s = (uint32_t)__cvta_generic_to_shared(smem_ptr);
    asm volatile("cp.async.ca.shared.global [%0], [%1], 4;" :: "r"(s), "l"(gmem_ptr));
}
__device__ __forceinline__ void cp_async16(void* smem_ptr, const void* gmem_ptr) {
    uint32_t s = (uint32_t)__cvta_generic_to_shared(smem_ptr);
    asm volatile("cp.async.cg.shared.global [%0], [%1], 16;" :: "r"(s), "l"(gmem_ptr));
}
__device__ __forceinline__ void cp_commit() { asm volatile("cp.async.commit_group;"); }
template <int N>
__device__ __forceinline__ void cp_wait() {
    asm volatile("cp.async.wait_group %0;" :: "n"(N));
}

// ---------------------------------------------------------------------------
// Kernel 1: per-pixel channel-parity sums
// ---------------------------------------------------------------------------
__global__ void parity_sum_kernel(const float* __restrict__ x) {
    int idx = blockIdx.x * blockDim.x + threadIdx.x;
    if (idx >= NB * HW) return;
    int b = idx / HW;
    int pix = idx - b * HW;
    const float* xp = x + (size_t)b * NC * HW + pix;
    float s0 = 0.f, s1 = 0.f;
#pragma unroll 8
    for (int c = 0; c < NC; c += 2) {
        s0 += xp[(size_t)c * HW];
        s1 += xp[(size_t)(c + 1) * HW];
    }
    g_T[(b * 2 + 0) * HW + pix] = s0;
    g_T[(b * 2 + 1) * HW + pix] = s1;
}

// ---------------------------------------------------------------------------
// Kernel 2: 3x3 edge-clamped box filter / 576 -> g_avg
// ---------------------------------------------------------------------------
__global__ void avg_kernel() {
    int idx = blockIdx.x * blockDim.x + threadIdx.x;
    if (idx >= NB * 2 * HW) return;
    int bu = idx / HW;
    int pix = idx - bu * HW;
    int i = pix / NW, j = pix - (pix / NW) * NW;
    const float* T = g_T + bu * HW;
    float s = 0.f;
#pragma unroll
    for (int r = -1; r <= 1; r++) {
        int y = min(max(i + r, 0), NH - 1);
#pragma unroll
        for (int q = -1; q <= 1; q++) {
            int xw = min(max(j + q, 0), NW - 1);
            s += T[y * NW + xw];
        }
    }
    g_avg[idx] = s * (1.0f / 576.0f);
}

// ---------------------------------------------------------------------------
// Kernel 3: W2[o,u] = sum_{c%2==u} sum_{r,s} w[o,c,r,s]   (fp32, original w)
// ---------------------------------------------------------------------------
__global__ void w2_kernel(const float* __restrict__ w) {
    __shared__ float s2[2];
    int o = blockIdx.x;
    int c = threadIdx.x;  // 0..127
    if (c < 2) s2[c] = 0.f;
    __syncthreads();
    const float* wp = w + ((size_t)o * NC + c) * 9;
    float s = 0.f;
#pragma unroll
    for (int k = 0; k < 9; k++) s += wp[k];
    atomicAdd(&s2[c & 1], s);
    __syncthreads();
    if (c < 2) g_W2[o * 2 + c] = s2[c];
}

// ---------------------------------------------------------------------------
// Kernel 3b: reorder weights -> g_wre[tap][oc][c], rounded to tf32
// ---------------------------------------------------------------------------
__global__ void wre_kernel(const float* __restrict__ w) {
    int idx = blockIdx.x * blockDim.x + threadIdx.x;
    if (idx >= NOC * NC * 9) return;
    int tap = idx % 9;
    int rem = idx / 9;          // oc*128 + c
    int oc = rem / NC;
    int c = rem - oc * NC;
    float v = w[((size_t)oc * NC + c) * 9 + tap];
    g_wre[(tap * NOC + oc) * NC + c] = __uint_as_float(f2tf(v));
}

// ---------------------------------------------------------------------------
// Kernel 4: implicit-GEMM conv via mma.sync tf32 + fused epilogue.
// CTA: 4 rows x 32 cols pixel tile (128 px), all 128 oc. 8 warps (4M x 2N).
// K loop: 4 c-chunks of 32 x 9 taps, cp.async double-buffered.
//
// k-permutation: mma k-slot l -> c=2l, slot l+4 -> c=2l+1, so A pairs
// (a0,a2),(a1,a3) and B pair (b0,b1) are contiguous LDS.64.
// x smem: [c2(16)][plane 456 floats = 6 rows x 76 (38 colpairs x 2)]
//   -> B pair-bank = 4l + g + const (conflict-free).
// w smem: [oc(128)][40 floats] -> A pair-bank = 4g + l + const (conflict-free).
// ---------------------------------------------------------------------------
constexpr int XPLANE = 456;                 // floats per c2 plane (228 pairs == 4 mod 16)
constexpr int XBUF = 16 * XPLANE;           // 7296 floats
constexpr int WROW = 40;                    // floats per oc row (20 pairs == 4 mod 16)
constexpr int WBUF = NOC * WROW;            // 5120 floats
constexpr int SMEM_FLOATS = 2 * XBUF + 2 * WBUF + NOC + 2 * NOC;
constexpr int SMEM_BYTES = SMEM_FLOATS * 4; // 100864 B

__global__ __launch_bounds__(256, 2) void conv_mma_kernel(
    const float* __restrict__ x, const float* __restrict__ bias,
    float* __restrict__ out) {
    extern __shared__ __align__(16) float smem[];
    float* xs = smem;                       // [2][XBUF]
    float* ws = smem + 2 * XBUF;            // [2][WBUF]
    float* s_bias = ws + 2 * WBUF;          // [128]
    float* s_w2 = s_bias + NOC;             // [256]

    int b = blockIdx.z;
    int col0 = (blockIdx.x & 1) * 32;
    int row0 = (blockIdx.x >> 1) * 4;

    int t = threadIdx.x;
    int wid = t >> 5, lane = t & 31;
    int g = lane >> 2, l = lane & 3;
    int wm = wid >> 1, wn = wid & 1;

    if (t < NOC) s_bias[t] = bias[t];
    if (t < 2 * NOC) s_w2[t] = g_W2[t];

    const float* xb = x + (size_t)b * NC * HW;

    // ---- async loaders ----
    auto load_x = [&](int cc, int buf) {
        float* dst = xs + buf * XBUF;
        const float* src = xb + (size_t)cc * 32 * HW;
#pragma unroll 1
        for (int e = t; e < 32 * 204; e += 256) {
            int c = e / 204;
            int rem = e - c * 204;
            int sr = rem / 34;
            int sc = rem - sr * 34;
            int gy = min(max(row0 - 1 + sr, 0), NH - 1);
            int gx = min(max(col0 - 1 + sc, 0), NW - 1);
            cp_async4(dst + (c >> 1) * XPLANE + sr * 76 + sc * 2 + (c & 1),
                      src + (size_t)c * HW + gy * NW + gx);
        }
    };
    auto load_w = [&](int cc, int tap, int buf) {
        float* dst = ws + buf * WBUF;
        const float* src = g_wre + (size_t)tap * NOC * NC + cc * 32;
#pragma unroll
        for (int e = t; e < NOC * 8; e += 256) {
            int oc = e >> 3;
            int q16 = e & 7;
            cp_async16(dst + oc * WROW + q16 * 4, src + oc * NC + q16 * 4);
        }
    };

    float acc[2][8][4];
#pragma unroll
    for (int mt = 0; mt < 2; mt++)
#pragma unroll
        for (int nt = 0; nt < 8; nt++)
#pragma unroll
            for (int k = 0; k < 4; k++) acc[mt][nt][k] = 0.f;

    load_x(0, 0);
    load_w(0, 0, 0);
    cp_commit();

#pragma unroll 1
    for (int step = 0; step < 36; step++) {
        int cc = step / 9;
        int tap = step - cc * 9;
        int nstep = step + 1;
        if (nstep < 36) {
            int ncc = nstep / 9;
            int ntap = nstep - ncc * 9;
            if (ntap == 0) load_x(ncc, ncc & 1);
            load_w(ncc, ntap, nstep & 1);
            cp_commit();
            cp_wait<1>();
        } else {
            cp_wait<0>();
        }
        __syncthreads();

        int r = tap / 3;           // col shift
        int sft = tap - r * 3;     // row shift
        // B base: c2 = l (+4q), pixel row = wn*2 + (nt>>2) + sft, col = (nt&3)*8 + g + r
        const float* Bbase = xs + (cc & 1) * XBUF + l * XPLANE +
                             (wn * 2 + sft) * 76 + (g + r) * 2;
        // A base: row = wm*32 + mt*16 + g (+8), c = 8q + 2l
        const float* Abase = ws + (step & 1) * WBUF + (wm * 32 + g) * WROW + 2 * l;

#pragma unroll
        for (int q = 0; q < 4; q++) {
            uint32_t A[2][4];
#pragma unroll
            for (int mt = 0; mt < 2; mt++) {
                float2 p0 = *(const float2*)(Abase + mt * (16 * WROW) + q * 8);
                float2 p1 = *(const float2*)(Abase + mt * (16 * WROW) + 8 * WROW + q * 8);
                A[mt][0] = __float_as_uint(p0.x);  // pre-rounded tf32
                A[mt][2] = __float_as_uint(p0.y);
                A[mt][1] = __float_as_uint(p1.x);
                A[mt][3] = __float_as_uint(p1.y);
            }
#pragma unroll
            for (int nt = 0; nt < 8; nt++) {
                float2 bp = *(const float2*)(Bbase + q * (4 * XPLANE) +
                                             (nt >> 2) * 76 + (nt & 3) * 16);
                uint32_t b0 = f2tf(bp.x);
                uint32_t b1 = f2tf(bp.y);
                mma_tf32(acc[0][nt], A[0][0], A[0][1], A[0][2], A[0][3], b0, b1);
                mma_tf32(acc[1][nt], A[1][0], A[1][1], A[1][2], A[1][3], b0, b1);
            }
        }
        __syncthreads();
    }

    // ---- epilogue: bias - W2*avg, leaky, + parity mean ----
    const float* avg0 = g_avg + (b * 2 + 0) * HW;
    const float* avg1 = g_avg + (b * 2 + 1) * HW;
#pragma unroll
    for (int nt = 0; nt < 8; nt++) {
        int i = row0 + wn * 2 + (nt >> 2);
        int j = col0 + (nt & 3) * 8 + 2 * l;
        float2 a0 = *(const float2*)(avg0 + i * NW + j);
        float2 a1 = *(const float2*)(avg1 + i * NW + j);
#pragma unroll
        for (int mt = 0; mt < 2; mt++) {
#pragma unroll
            for (int half = 0; half < 2; half++) {
                int o = wm * 32 + mt * 16 + half * 8 + g;
                float bw = s_bias[o];
                float w20 = s_w2[2 * o], w21 = s_w2[2 * o + 1];
                float v0 = acc[mt][nt][half * 2 + 0] + bw - w20 * a0.x - w21 * a1.x;
                float v1 = acc[mt][nt][half * 2 + 1] + bw - w20 * a0.y - w21 * a1.y;
                v0 = v0 > 0.f ? v0 : 0.01f * v0;
                v1 = v1 > 0.f ? v1 : 0.01f * v1;
                if (o & 1) { v0 += a1.x; v1 += a1.y; }
                else       { v0 += a0.x; v1 += a0.y; }
                float2 vv = make_float2(v0, v1);
                *(float2*)(out + ((size_t)(b * NOC + o)) * HW + i * NW + j) = vv;
            }
        }
    }
}

// ---------------------------------------------------------------------------
extern "C" void kernel_launch(void* const* d_in, const int* in_sizes, int n_in,
                              void* d_out, int out_size) {
    const float* x = (const float*)d_in[0];     // (16,128,64,64)
    const float* w = (const float*)d_in[1];     // (128,128,3,3)
    const float* bias = (const float*)d_in[2];  // (128,)
    float* out = (float*)d_out;                 // (16,128,64,64)

    cudaFuncSetAttribute(conv_mma_kernel,
                         cudaFuncAttributeMaxDynamicSharedMemorySize, SMEM_BYTES);

    parity_sum_kernel<<<(NB * HW + 255) / 256, 256>>>(x);
    avg_kernel<<<(NB * 2 * HW + 255) / 256, 256>>>();
    w2_kernel<<<NOC, 128>>>(w);
    wre_kernel<<<(NOC * NC * 9 + 255) / 256, 256>>>(w);

    dim3 grid(32, 1, NB);  // 32 pixel tiles (2x in x, 16 in y) x 16 batches
    conv_mma_kernel<<<grid, 256, SMEM_BYTES>>>(x, bias, out);
}

// round 11
// speedup vs baseline: 2.7668x; 1.0050x over previous
#include <cuda_runtime.h>
#include <cstdint>

// Problem constants
constexpr int NB = 16;
constexpr int NC = 128;
constexpr int NH = 64;
constexpr int NW = 64;
constexpr int HW = NH * NW;
constexpr int NOC = 128;

// Scratch (allocation-free rule: __device__ globals)
__device__ float g_T[NB * 2 * HW];        // per-parity channel sums
__device__ float g_avg[NB * 2 * HW];      // 3x3 box mean / 576
__device__ float g_W2[NOC * 2];           // sum of weights per (o, parity)
__device__ __align__(16) float g_wre[9 * NOC * NC];  // w reordered [tap][oc][c], tf32-rounded

// ---------------------------------------------------------------------------
// helpers
// ---------------------------------------------------------------------------
__device__ __forceinline__ uint32_t f2tf(float f) {
    uint32_t u;
    asm("cvt.rna.tf32.f32 %0, %1;" : "=r"(u) : "f"(f));
    return u;
}
__device__ __forceinline__ void mma_tf32(float* c, uint32_t a0, uint32_t a1,
                                         uint32_t a2, uint32_t a3,
                                         uint32_t b0, uint32_t b1) {
    asm volatile(
        "mma.sync.aligned.m16n8k8.row.col.f32.tf32.tf32.f32 "
        "{%0,%1,%2,%3}, {%4,%5,%6,%7}, {%8,%9}, {%0,%1,%2,%3};"
        : "+f"(c[0]), "+f"(c[1]), "+f"(c[2]), "+f"(c[3])
        : "r"(a0), "r"(a1), "r"(a2), "r"(a3), "r"(b0), "r"(b1));
}
__device__ __forceinline__ void cp_async4(void* smem_ptr, const void* gmem_ptr) {
    uint32_t s = (uint32_t)__cvta_generic_to_shared(smem_ptr);
    asm volatile("cp.async.ca.shared.global [%0], [%1], 4;" :: "r"(s), "l"(gmem_ptr));
}
__device__ __forceinline__ void cp_async16(void* smem_ptr, const void* gmem_ptr) {
    uint32_t s = (uint32_t)__cvta_generic_to_shared(smem_ptr);
    asm volatile("cp.async.cg.shared.global [%0], [%1], 16;" :: "r"(s), "l"(gmem_ptr));
}
__device__ __forceinline__ void cp_commit() { asm volatile("cp.async.commit_group;"); }
template <int N>
__device__ __forceinline__ void cp_wait() {
    asm volatile("cp.async.wait_group %0;" :: "n"(N));
}

// ---------------------------------------------------------------------------
// Kernel 1: per-pixel channel-parity sums
// ---------------------------------------------------------------------------
__global__ void parity_sum_kernel(const float* __restrict__ x) {
    int idx = blockIdx.x * blockDim.x + threadIdx.x;
    if (idx >= NB * HW) return;
    int b = idx / HW;
    int pix = idx - b * HW;
    const float* xp = x + (size_t)b * NC * HW + pix;
    float s0 = 0.f, s1 = 0.f;
#pragma unroll 8
    for (int c = 0; c < NC; c += 2) {
        s0 += xp[(size_t)c * HW];
        s1 += xp[(size_t)(c + 1) * HW];
    }
    g_T[(b * 2 + 0) * HW + pix] = s0;
    g_T[(b * 2 + 1) * HW + pix] = s1;
}

// ---------------------------------------------------------------------------
// Kernel 2: 3x3 edge-clamped box filter / 576 -> g_avg
// ---------------------------------------------------------------------------
__global__ void avg_kernel() {
    int idx = blockIdx.x * blockDim.x + threadIdx.x;
    if (idx >= NB * 2 * HW) return;
    int bu = idx / HW;
    int pix = idx - bu * HW;
    int i = pix / NW, j = pix - (pix / NW) * NW;
    const float* T = g_T + bu * HW;
    float s = 0.f;
#pragma unroll
    for (int r = -1; r <= 1; r++) {
        int y = min(max(i + r, 0), NH - 1);
#pragma unroll
        for (int q = -1; q <= 1; q++) {
            int xw = min(max(j + q, 0), NW - 1);
            s += T[y * NW + xw];
        }
    }
    g_avg[idx] = s * (1.0f / 576.0f);
}

// ---------------------------------------------------------------------------
// Kernel 3: W2[o,u] = sum_{c%2==u} sum_{r,s} w[o,c,r,s]   (fp32, original w)
// ---------------------------------------------------------------------------
__global__ void w2_kernel(const float* __restrict__ w) {
    __shared__ float s2[2];
    int o = blockIdx.x;
    int c = threadIdx.x;  // 0..127
    if (c < 2) s2[c] = 0.f;
    __syncthreads();
    const float* wp = w + ((size_t)o * NC + c) * 9;
    float s = 0.f;
#pragma unroll
    for (int k = 0; k < 9; k++) s += wp[k];
    atomicAdd(&s2[c & 1], s);
    __syncthreads();
    if (c < 2) g_W2[o * 2 + c] = s2[c];
}

// ---------------------------------------------------------------------------
// Kernel 3b: reorder weights -> g_wre[tap][oc][c], rounded to tf32
// ---------------------------------------------------------------------------
__global__ void wre_kernel(const float* __restrict__ w) {
    int idx = blockIdx.x * blockDim.x + threadIdx.x;
    if (idx >= NOC * NC * 9) return;
    int tap = idx % 9;
    int rem = idx / 9;          // oc*128 + c
    int oc = rem / NC;
    int c = rem - oc * NC;
    float v = w[((size_t)oc * NC + c) * 9 + tap];
    g_wre[(tap * NOC + oc) * NC + c] = __uint_as_float(f2tf(v));
}

// ---------------------------------------------------------------------------
// Kernel 4: implicit-GEMM conv via mma.sync tf32 + fused epilogue.
// CTA: 4 rows x 32 cols pixel tile (128 px), all 128 oc. 8 warps (4M x 2N).
// K loop: 4 c-chunks of 32 x 9 taps, cp.async double-buffered.
//
// k-permutation: mma k-slot l -> c=2l, slot l+4 -> c=2l+1, so A pairs
// (a0,a2),(a1,a3) and B pair (b0,b1) are contiguous LDS.64.
// x smem: [c2(16)][plane 456 floats = 6 rows x 76 (38 colpairs x 2)]
//   -> B pair-bank = 4l + g + const (conflict-free).
// w smem: [oc(128)][40 floats] -> A pair-bank = 4g + l + const (conflict-free).
// ---------------------------------------------------------------------------
constexpr int XPLANE = 456;                 // floats per c2 plane (228 pairs == 4 mod 16)
constexpr int XBUF = 16 * XPLANE;           // 7296 floats
constexpr int WROW = 40;                    // floats per oc row (20 pairs == 4 mod 16)
constexpr int WBUF = NOC * WROW;            // 5120 floats
constexpr int SMEM_FLOATS = 2 * XBUF + 2 * WBUF + NOC + 2 * NOC;
constexpr int SMEM_BYTES = SMEM_FLOATS * 4; // 100864 B

__global__ __launch_bounds__(256, 2) void conv_mma_kernel(
    const float* __restrict__ x, const float* __restrict__ bias,
    float* __restrict__ out) {
    extern __shared__ __align__(16) float smem[];
    float* xs = smem;                       // [2][XBUF]
    float* ws = smem + 2 * XBUF;            // [2][WBUF]
    float* s_bias = ws + 2 * WBUF;          // [128]
    float* s_w2 = s_bias + NOC;             // [256]

    int b = blockIdx.z;
    int col0 = (blockIdx.x & 1) * 32;
    int row0 = (blockIdx.x >> 1) * 4;

    int t = threadIdx.x;
    int wid = t >> 5, lane = t & 31;
    int g = lane >> 2, l = lane & 3;
    int wm = wid >> 1, wn = wid & 1;

    if (t < NOC) s_bias[t] = bias[t];
    if (t < 2 * NOC) s_w2[t] = g_W2[t];

    const float* xb = x + (size_t)b * NC * HW;

    // ---- async loaders ----
    auto load_x = [&](int cc, int buf) {
        float* dst = xs + buf * XBUF;
        const float* src = xb + (size_t)cc * 32 * HW;
#pragma unroll 1
        for (int e = t; e < 32 * 204; e += 256) {
            int c = e / 204;
            int rem = e - c * 204;
            int sr = rem / 34;
            int sc = rem - sr * 34;
            int gy = min(max(row0 - 1 + sr, 0), NH - 1);
            int gx = min(max(col0 - 1 + sc, 0), NW - 1);
            cp_async4(dst + (c >> 1) * XPLANE + sr * 76 + sc * 2 + (c & 1),
                      src + (size_t)c * HW + gy * NW + gx);
        }
    };
    auto load_w = [&](int cc, int tap, int buf) {
        float* dst = ws + buf * WBUF;
        const float* src = g_wre + (size_t)tap * NOC * NC + cc * 32;
#pragma unroll
        for (int e = t; e < NOC * 8; e += 256) {
            int oc = e >> 3;
            int q16 = e & 7;
            cp_async16(dst + oc * WROW + q16 * 4, src + oc * NC + q16 * 4);
        }
    };

    float acc[2][8][4];
#pragma unroll
    for (int mt = 0; mt < 2; mt++)
#pragma unroll
        for (int nt = 0; nt < 8; nt++)
#pragma unroll
            for (int k = 0; k < 4; k++) acc[mt][nt][k] = 0.f;

    load_x(0, 0);
    load_w(0, 0, 0);
    cp_commit();

#pragma unroll 1
    for (int step = 0; step < 36; step++) {
        int cc = step / 9;
        int tap = step - cc * 9;
        int nstep = step + 1;
        if (nstep < 36) {
            int ncc = nstep / 9;
            int ntap = nstep - ncc * 9;
            if (ntap == 0) load_x(ncc, ncc & 1);
            load_w(ncc, ntap, nstep & 1);
            cp_commit();
            cp_wait<1>();
        } else {
            cp_wait<0>();
        }
        __syncthreads();

        int r = tap / 3;           // col shift
        int sft = tap - r * 3;     // row shift
        // B base: c2 = l (+4q), pixel row = wn*2 + (nt>>2) + sft, col = (nt&3)*8 + g + r
        const float* Bbase = xs + (cc & 1) * XBUF + l * XPLANE +
                             (wn * 2 + sft) * 76 + (g + r) * 2;
        // A base: row = wm*32 + mt*16 + g (+8), c = 8q + 2l
        const float* Abase = ws + (step & 1) * WBUF + (wm * 32 + g) * WROW + 2 * l;

#pragma unroll
        for (int q = 0; q < 4; q++) {
            uint32_t A[2][4];
#pragma unroll
            for (int mt = 0; mt < 2; mt++) {
                float2 p0 = *(const float2*)(Abase + mt * (16 * WROW) + q * 8);
                float2 p1 = *(const float2*)(Abase + mt * (16 * WROW) + 8 * WROW + q * 8);
                A[mt][0] = __float_as_uint(p0.x);  // pre-rounded tf32
                A[mt][2] = __float_as_uint(p0.y);
                A[mt][1] = __float_as_uint(p1.x);
                A[mt][3] = __float_as_uint(p1.y);
            }
#pragma unroll
            for (int nt = 0; nt < 8; nt++) {
                float2 bp = *(const float2*)(Bbase + q * (4 * XPLANE) +
                                             (nt >> 2) * 76 + (nt & 3) * 16);
                uint32_t b0 = f2tf(bp.x);
                uint32_t b1 = f2tf(bp.y);
                mma_tf32(acc[0][nt], A[0][0], A[0][1], A[0][2], A[0][3], b0, b1);
                mma_tf32(acc[1][nt], A[1][0], A[1][1], A[1][2], A[1][3], b0, b1);
            }
        }
        __syncthreads();
    }

    // ---- epilogue: bias - W2*avg, leaky, + parity mean ----
    const float* avg0 = g_avg + (b * 2 + 0) * HW;
    const float* avg1 = g_avg + (b * 2 + 1) * HW;
#pragma unroll
    for (int nt = 0; nt < 8; nt++) {
        int i = row0 + wn * 2 + (nt >> 2);
        int j = col0 + (nt & 3) * 8 + 2 * l;
        float2 a0 = *(const float2*)(avg0 + i * NW + j);
        float2 a1 = *(const float2*)(avg1 + i * NW + j);
#pragma unroll
        for (int mt = 0; mt < 2; mt++) {
#pragma unroll
            for (int half = 0; half < 2; half++) {
                int o = wm * 32 + mt * 16 + half * 8 + g;
                float bw = s_bias[o];
                float w20 = s_w2[2 * o], w21 = s_w2[2 * o + 1];
                float v0 = acc[mt][nt][half * 2 + 0] + bw - w20 * a0.x - w21 * a1.x;
                float v1 = acc[mt][nt][half * 2 + 1] + bw - w20 * a0.y - w21 * a1.y;
                v0 = v0 > 0.f ? v0 : 0.01f * v0;
                v1 = v1 > 0.f ? v1 : 0.01f * v1;
                if (o & 1) { v0 += a1.x; v1 += a1.y; }
                else       { v0 += a0.x; v1 += a0.y; }
                float2 vv = make_float2(v0, v1);
                *(float2*)(out + ((size_t)(b * NOC + o)) * HW + i * NW + j) = vv;
            }
        }
    }
}

// ---------------------------------------------------------------------------
extern "C" void kernel_launch(void* const* d_in, const int* in_sizes, int n_in,
                              void* d_out, int out_size) {
    const float* x = (const float*)d_in[0];     // (16,128,64,64)
    const float* w = (const float*)d_in[1];     // (128,128,3,3)
    const float* bias = (const float*)d_in[2];  // (128,)
    float* out = (float*)d_out;                 // (16,128,64,64)

    cudaFuncSetAttribute(conv_mma_kernel,
                         cudaFuncAttributeMaxDynamicSharedMemorySize, SMEM_BYTES);

    parity_sum_kernel<<<(NB * HW + 255) / 256, 256>>>(x);
    avg_kernel<<<(NB * 2 * HW + 255) / 256, 256>>>();
    w2_kernel<<<NOC, 128>>>(w);
    wre_kernel<<<(NOC * NC * 9 + 255) / 256, 256>>>(w);

    dim3 grid(32, 1, NB);  // 32 pixel tiles (2x in x, 16 in y) x 16 batches
    conv_mma_kernel<<<grid, 256, SMEM_BYTES>>>(x, bias, out);
}